// round 4
// baseline (speedup 1.0000x reference)
#include <cuda_runtime.h>
#include <cuda_bf16.h>
#include <math.h>
#include <stdint.h>

// Problem constants
#define Bv      2
#define Tv      2048
#define NTOK    (Bv * Tv)      // 4096
#define Dv      512
#define Hv      8
#define HDv     64
#define FFNv    2048
#define VOCABv  256
#define Lv      2
#define CHUNK   64
#define NCHUNK  (Tv / CHUNK)   // 32
#define QKVN    1536

// weight region offsets (elements) in the hi/lo weight pools
#define OFF_QKV 0
#define OFF_WU  (OFF_QKV + Lv * Dv * QKVN)
#define OFF_WD  (OFF_WU + Lv * Dv * FFNv)
#define OFF_WO  (OFF_WD + Lv * FFNv * Dv)
#define W_TOTAL (OFF_WO + Dv * VOCABv)

// -------------------- scratch (device globals; no allocs) --------------------
__device__ float g_x[NTOK * Dv];
__device__ float g_a[NTOK * Dv];
__device__ float g_qkv[NTOK * QKVN];
__device__ float g_qf[NTOK * Dv];
__device__ float g_kf[NTOK * Dv];
__device__ float g_S[Bv * Hv * NCHUNK * HDv * HDv];
__device__ float g_z[Bv * Hv * NCHUNK * HDv];
__device__ float g_bqkv[Lv * QKVN];
__device__ __nv_bfloat16 g_xh[NTOK * Dv];
__device__ __nv_bfloat16 g_xl[NTOK * Dv];
__device__ __nv_bfloat16 g_hh[NTOK * FFNv];
__device__ __nv_bfloat16 g_hl[NTOK * FFNv];
__device__ __nv_bfloat16 g_wh[W_TOTAL];
__device__ __nv_bfloat16 g_wl[W_TOTAL];

__device__ __forceinline__ void split_bf16(float v, __nv_bfloat16& h, __nv_bfloat16& l) {
    h = __float2bfloat16(v);
    l = __float2bfloat16(v - __bfloat162float(h));
}

// -------------------- weight fp32 -> bf16 hi/lo (vectorized) --------------------
__global__ void convw4(const float* __restrict__ src, __nv_bfloat16* __restrict__ dh,
                       __nv_bfloat16* __restrict__ dl, int n4) {
    int i = blockIdx.x * blockDim.x + threadIdx.x;
    if (i >= n4) return;
    float4 v = *(const float4*)(src + 4 * i);
    __nv_bfloat16 h0, h1, h2, h3, l0, l1, l2, l3;
    split_bf16(v.x, h0, l0); split_bf16(v.y, h1, l1);
    split_bf16(v.z, h2, l2); split_bf16(v.w, h3, l3);
    ((__nv_bfloat162*)(dh + 4 * i))[0] = __nv_bfloat162(h0, h1);
    ((__nv_bfloat162*)(dh + 4 * i))[1] = __nv_bfloat162(h2, h3);
    ((__nv_bfloat162*)(dl + 4 * i))[0] = __nv_bfloat162(l0, l1);
    ((__nv_bfloat162*)(dl + 4 * i))[1] = __nv_bfloat162(l2, l3);
}

// QKV weight: src [L*512, 512] row-major -> dst rows stride 1536 at column colofs
__global__ void convw_qkv(const float* __restrict__ src, __nv_bfloat16* __restrict__ dh,
                          __nv_bfloat16* __restrict__ dl, int colofs) {
    int i = blockIdx.x * blockDim.x + threadIdx.x;   // i < L*512*512/4
    if (i >= Lv * Dv * Dv / 4) return;
    int e = 4 * i;
    int k = e >> 9, col = e & 511;
    float4 v = *(const float4*)(src + e);
    size_t dst = (size_t)k * QKVN + colofs + col;
    __nv_bfloat16 h0, h1, h2, h3, l0, l1, l2, l3;
    split_bf16(v.x, h0, l0); split_bf16(v.y, h1, l1);
    split_bf16(v.z, h2, l2); split_bf16(v.w, h3, l3);
    ((__nv_bfloat162*)(dh + dst))[0] = __nv_bfloat162(h0, h1);
    ((__nv_bfloat162*)(dh + dst))[1] = __nv_bfloat162(h2, h3);
    ((__nv_bfloat162*)(dl + dst))[0] = __nv_bfloat162(l0, l1);
    ((__nv_bfloat162*)(dl + dst))[1] = __nv_bfloat162(l2, l3);
}

__global__ void bias_qkv(const float* __restrict__ bq, const float* __restrict__ bk,
                         const float* __restrict__ bvp) {
    int idx = blockIdx.x * blockDim.x + threadIdx.x;
    if (idx >= Lv * QKVN) return;
    int l = idx / QKVN, c = idx % QKVN;
    float v;
    if (c < 512) v = bq[l * Dv + c];
    else if (c < 1024) v = bk[l * Dv + c - 512];
    else v = bvp[l * Dv + c - 1024];
    g_bqkv[idx] = v;
}

// -------------------- embedding + sinusoidal positions --------------------
__global__ void embed_kernel(const int* __restrict__ tokens,
                             const float* __restrict__ emb) {
    int idx = blockIdx.x * blockDim.x + threadIdx.x;
    if (idx >= NTOK * Dv) return;
    int n = idx >> 9;
    int j = idx & 511;
    int t = n & (Tv - 1);
    float val;
    const float c = 9.210340371976184f / 256.f;
    if (j < 256) {
        int tok = tokens[n];
        val = emb[tok * 256 + j];
    } else if (j < 384) {
        int i = j - 256;
        val = sinf((float)t * expf(-(2.f * (float)i) * c));
    } else {
        int i = j - 384;
        val = cosf((float)t * expf(-(2.f * (float)i) * c));
    }
    g_x[idx] = val;
    __nv_bfloat16 h, l;
    split_bf16(val, h, l);
    g_xh[idx] = h;
    g_xl[idx] = l;
}

// -------------------- tensor-core GEMM, 3-stage cp.async pipeline --------------------
__device__ __forceinline__ void ldsm_x4(uint32_t* r, const void* p) {
    uint32_t a = (uint32_t)__cvta_generic_to_shared(p);
    asm volatile("ldmatrix.sync.aligned.m8n8.x4.shared.b16 {%0,%1,%2,%3},[%4];"
        : "=r"(r[0]), "=r"(r[1]), "=r"(r[2]), "=r"(r[3]) : "r"(a));
}
__device__ __forceinline__ void ldsm_x4_t(uint32_t* r, const void* p) {
    uint32_t a = (uint32_t)__cvta_generic_to_shared(p);
    asm volatile("ldmatrix.sync.aligned.m8n8.x4.trans.shared.b16 {%0,%1,%2,%3},[%4];"
        : "=r"(r[0]), "=r"(r[1]), "=r"(r[2]), "=r"(r[3]) : "r"(a));
}
__device__ __forceinline__ void mma16816(float* c, const uint32_t* a, const uint32_t* b) {
    asm volatile("mma.sync.aligned.m16n8k16.row.col.f32.bf16.bf16.f32 "
        "{%0,%1,%2,%3},{%4,%5,%6,%7},{%8,%9},{%0,%1,%2,%3};"
        : "+f"(c[0]), "+f"(c[1]), "+f"(c[2]), "+f"(c[3])
        : "r"(a[0]), "r"(a[1]), "r"(a[2]), "r"(a[3]), "r"(b[0]), "r"(b[1]));
}
__device__ __forceinline__ void cp16(void* smem, const void* gmem) {
    uint32_t s = (uint32_t)__cvta_generic_to_shared(smem);
    asm volatile("cp.async.cg.shared.global [%0], [%1], 16;" :: "r"(s), "l"(gmem));
}
#define CP_COMMIT() asm volatile("cp.async.commit_group;")
#define CP_WAIT(n)  asm volatile("cp.async.wait_group %0;" :: "n"(n))

#define PADA 40
#define PADB 136
// 3 stages: A hi 3*128*40*2=30720 ; B hi 3*32*136*2=26112
#define SM_ASH 0
#define SM_ASL 30720
#define SM_BSH 61440
#define SM_BSL 87552
#define SM_TOTAL 113664

__global__ void __launch_bounds__(256, 1)
gemm_tc(const __nv_bfloat16* __restrict__ Ahg, const __nv_bfloat16* __restrict__ Alg,
        const __nv_bfloat16* __restrict__ Bhg, const __nv_bfloat16* __restrict__ Blg,
        const float* __restrict__ bias, float* __restrict__ C,
        __nv_bfloat16* __restrict__ Ch, __nv_bfloat16* __restrict__ Cl,
        int M, int N, int K, int mode) {
    extern __shared__ char smraw[];
    __nv_bfloat16* AsH = (__nv_bfloat16*)(smraw + SM_ASH);
    __nv_bfloat16* AsL = (__nv_bfloat16*)(smraw + SM_ASL);
    __nv_bfloat16* BsH = (__nv_bfloat16*)(smraw + SM_BSH);
    __nv_bfloat16* BsL = (__nv_bfloat16*)(smraw + SM_BSL);

    int tid = threadIdx.x;
    int wid = tid >> 5, lane = tid & 31;
    int m_w = (wid >> 1) * 32, n_w = (wid & 1) * 64;
    int row0 = blockIdx.y * 128, col0 = blockIdx.x * 128;

    float acc[2][8][4];
#pragma unroll
    for (int i = 0; i < 2; i++)
#pragma unroll
        for (int j = 0; j < 8; j++)
#pragma unroll
            for (int q = 0; q < 4; q++) acc[i][j][q] = 0.f;

    int ar = tid >> 2, ac = (tid & 3) * 8;
    int br = tid >> 4, bc = (tid & 15) * 8;

    auto loadStage = [&](int st, int k0) {
#pragma unroll
        for (int s = 0; s < 2; s++) {
            int a_row = ar + s * 64;
            size_t ga = (size_t)(row0 + a_row) * K + k0 + ac;
            int sa = (st * 128 + a_row) * PADA + ac;
            cp16(AsH + sa, Ahg + ga);
            cp16(AsL + sa, Alg + ga);
            int b_row = br + s * 16;
            size_t gb = (size_t)(k0 + b_row) * N + col0 + bc;
            int sb = (st * 32 + b_row) * PADB + bc;
            cp16(BsH + sb, Bhg + gb);
            cp16(BsL + sb, Blg + gb);
        }
        CP_COMMIT();
    };

    auto compute = [&](int st) {
#pragma unroll
        for (int kk = 0; kk < 32; kk += 16) {
            uint32_t Ahf[2][4], Alf[2][4], Bhf[8][2], Blf[8][2];
#pragma unroll
            for (int i = 0; i < 2; i++) {
                int idx = (st * 128 + m_w + i * 16 + (lane & 15)) * PADA + kk + (lane >> 4) * 8;
                ldsm_x4(Ahf[i], AsH + idx);
                ldsm_x4(Alf[i], AsL + idx);
            }
#pragma unroll
            for (int p = 0; p < 4; p++) {
                int idx = (st * 32 + kk + (lane & 15)) * PADB + n_w + p * 16 + (lane >> 4) * 8;
                uint32_t r[4];
                ldsm_x4_t(r, BsH + idx);
                Bhf[2 * p][0] = r[0]; Bhf[2 * p][1] = r[1];
                Bhf[2 * p + 1][0] = r[2]; Bhf[2 * p + 1][1] = r[3];
                ldsm_x4_t(r, BsL + idx);
                Blf[2 * p][0] = r[0]; Blf[2 * p][1] = r[1];
                Blf[2 * p + 1][0] = r[2]; Blf[2 * p + 1][1] = r[3];
            }
#pragma unroll
            for (int i = 0; i < 2; i++)
#pragma unroll
                for (int j = 0; j < 8; j++) {
                    mma16816(acc[i][j], Ahf[i], Bhf[j]);
                    mma16816(acc[i][j], Alf[i], Bhf[j]);
                    mma16816(acc[i][j], Ahf[i], Blf[j]);
                }
        }
    };

    int nsteps = K / 32;
    loadStage(0, 0);
    loadStage(1, 32);
    for (int s = 0; s < nsteps; s++) {
        if (s + 1 < nsteps) { CP_WAIT(1); } else { CP_WAIT(0); }
        __syncthreads();
        if (s + 2 < nsteps) loadStage((s + 2) % 3, (s + 2) * 32);
        compute(s % 3);
    }

    // epilogue
    int g = lane >> 2, tg = lane & 3;
#pragma unroll
    for (int i = 0; i < 2; i++) {
#pragma unroll
        for (int j = 0; j < 8; j++) {
            int cc = col0 + n_w + j * 8 + tg * 2;
            float b0 = bias[cc], b1 = bias[cc + 1];
#pragma unroll
            for (int half = 0; half < 2; half++) {
                int r = row0 + m_w + i * 16 + g + half * 8;
                float v0 = acc[i][j][half * 2 + 0] + b0;
                float v1 = acc[i][j][half * 2 + 1] + b1;
                if (mode == 1) {
                    v0 = 0.5f * v0 * (1.f + erff(v0 * 0.7071067811865475f));
                    v1 = 0.5f * v1 * (1.f + erff(v1 * 0.7071067811865475f));
                    __nv_bfloat16 h0, l0, h1, l1;
                    split_bf16(v0, h0, l0);
                    split_bf16(v1, h1, l1);
                    *(__nv_bfloat162*)(Ch + (size_t)r * N + cc) = __nv_bfloat162(h0, h1);
                    *(__nv_bfloat162*)(Cl + (size_t)r * N + cc) = __nv_bfloat162(l0, l1);
                } else {
                    *(float2*)(C + (size_t)r * N + cc) = make_float2(v0, v1);
                }
            }
        }
    }
}

// -------------------- FAVOR+ feature map (smem-tiled; reads g_qkv) --------------------
__global__ void __launch_bounds__(128)
favor_feat(const float* __restrict__ rfs) {
    int tile = blockIdx.x, h = blockIdx.y;
    __shared__ float rf[64][64];
    __shared__ float sq[32][68], sk[32][68];
    int tid = threadIdx.x;
    const float* rfh = rfs + h * 4096;
    for (int i = tid; i < 4096; i += 128) rf[i >> 6][i & 63] = rfh[i];
    const float sc = 0.3535533905932738f;
    for (int i = tid; i < 2048; i += 128) {
        int tl = i >> 6, d = i & 63;
        size_t gq = (size_t)(tile * 32 + tl) * QKVN + h * HDv + d;
        sq[tl][d] = g_qkv[gq] * sc;
        sk[tl][d] = g_qkv[gq + 512] * sc;
    }
    __syncthreads();
    int tl = tid >> 2, ms = (tid & 3) << 4;
    float s2q = 0.f, s2k = 0.f;
#pragma unroll 8
    for (int d = 0; d < 64; d++) {
        float a = sq[tl][d], b = sk[tl][d];
        s2q += a * a;
        s2k += b * b;
    }
    float dq[16], dk[16];
#pragma unroll
    for (int mi = 0; mi < 16; mi++) { dq[mi] = 0.f; dk[mi] = 0.f; }
#pragma unroll 4
    for (int d = 0; d < 64; d++) {
        float a = sq[tl][d], b = sk[tl][d];
#pragma unroll
        for (int m4 = 0; m4 < 4; m4++) {
            float4 rv = *(const float4*)&rf[d][ms + m4 * 4];
            float rr[4] = {rv.x, rv.y, rv.z, rv.w};
#pragma unroll
            for (int q = 0; q < 4; q++) {
                dq[m4 * 4 + q] += a * rr[q];
                dk[m4 * 4 + q] += b * rr[q];
            }
        }
    }
    int base = (tile * 32 + tl) * Dv + h * HDv + ms;
#pragma unroll
    for (int mi = 0; mi < 16; mi++) {
        g_qf[base + mi] = expf(dq[mi] - 0.5f * s2q);
        g_kf[base + mi] = expf(dk[mi] - 0.5f * s2k);
    }
}

// -------------------- phase 1: per-chunk sums --------------------
__global__ void __launch_bounds__(64)
attn_chunk() {
    int c = blockIdx.x, bh = blockIdx.y;
    int b = bh / Hv, h = bh % Hv;
    int d = threadIdx.x;
    float S[64];
#pragma unroll
    for (int m = 0; m < 64; m++) S[m] = 0.f;
    float z = 0.f;
    __shared__ float sk[64];
    for (int t = c * CHUNK; t < (c + 1) * CHUNK; t++) {
        int kbase = (b * Tv + t) * Dv + h * HDv;
        size_t vbase = (size_t)(b * Tv + t) * QKVN + 1024 + h * HDv;
        sk[d] = g_kf[kbase + d];
        __syncthreads();
        float vd = g_qkv[vbase + d];
        z += sk[d];
#pragma unroll
        for (int m = 0; m < 64; m++) S[m] += sk[m] * vd;
        __syncthreads();
    }
    int sb = (bh * NCHUNK + c) * 4096;
#pragma unroll
    for (int m = 0; m < 64; m++) g_S[sb + m * 64 + d] = S[m];
    g_z[(bh * NCHUNK + c) * 64 + d] = z;
}

// -------------------- phase 2: exclusive scans over chunks --------------------
__global__ void __launch_bounds__(64)
attn_scan_S() {
    int bh = blockIdx.x >> 6, m = blockIdx.x & 63, d = threadIdx.x;
    float v[NCHUNK];
#pragma unroll
    for (int c = 0; c < NCHUNK; c++)
        v[c] = g_S[((bh * NCHUNK + c) << 12) + m * 64 + d];
    float acc = 0.f;
#pragma unroll
    for (int c = 0; c < NCHUNK; c++) {
        g_S[((bh * NCHUNK + c) << 12) + m * 64 + d] = acc;
        acc += v[c];
    }
}
__global__ void __launch_bounds__(64)
attn_scan_z() {
    int bh = blockIdx.x, d = threadIdx.x;
    float v[NCHUNK];
#pragma unroll
    for (int c = 0; c < NCHUNK; c++) v[c] = g_z[(bh * NCHUNK + c) * 64 + d];
    float acc = 0.f;
#pragma unroll
    for (int c = 0; c < NCHUNK; c++) {
        g_z[(bh * NCHUNK + c) * 64 + d] = acc;
        acc += v[c];
    }
}

// -------------------- phase 3: replay + output --------------------
__global__ void __launch_bounds__(64)
attn_apply() {
    int c = blockIdx.x, bh = blockIdx.y;
    int b = bh / Hv, h = bh % Hv;
    int d = threadIdx.x;
    int lane = d & 31, w = d >> 5;
    float S[64];
    int sb = (bh * NCHUNK + c) * 4096;
#pragma unroll
    for (int m = 0; m < 64; m++) S[m] = g_S[sb + m * 64 + d];
    float z = g_z[(bh * NCHUNK + c) * 64 + d];
    __shared__ float sk[64], sq[64], sred[2];
    for (int t = c * CHUNK; t < (c + 1) * CHUNK; t++) {
        int base = (b * Tv + t) * Dv + h * HDv;
        size_t vbase = (size_t)(b * Tv + t) * QKVN + 1024 + h * HDv;
        sk[d] = g_kf[base + d];
        sq[d] = g_qf[base + d];
        __syncthreads();
        z += sk[d];
        float p = sq[d] * z;
#pragma unroll
        for (int off = 16; off; off >>= 1) p += __shfl_down_sync(0xffffffffu, p, off);
        if (lane == 0) sred[w] = p;
        float vd = g_qkv[vbase + d];
        float num = 0.f;
#pragma unroll
        for (int m = 0; m < 64; m++) {
            S[m] += sk[m] * vd;
            num += sq[m] * S[m];
        }
        __syncthreads();
        float den = sred[0] + sred[1];
        g_a[base + d] = num / (den + 1e-16f);
    }
}

// -------------------- LayerNorm + residual add (+ bf16 hi/lo of new x) ----------
__global__ void __launch_bounds__(128)
ln_add(const float* __restrict__ a, const float* __restrict__ g,
       const float* __restrict__ bl, float* __restrict__ x) {
    int n = blockIdx.x, tid = threadIdx.x;
    int lane = tid & 31, w = tid >> 5;
    const float* ar = a + (size_t)n * Dv;
    float v[4];
    float s = 0.f, s2 = 0.f;
#pragma unroll
    for (int i = 0; i < 4; i++) {
        float t = ar[tid + i * 128];
        v[i] = t;
        s += t;
        s2 += t * t;
    }
    __shared__ float sh[8];
#pragma unroll
    for (int off = 16; off; off >>= 1) {
        s += __shfl_down_sync(0xffffffffu, s, off);
        s2 += __shfl_down_sync(0xffffffffu, s2, off);
    }
    if (lane == 0) { sh[w] = s; sh[4 + w] = s2; }
    __syncthreads();
    float S = sh[0] + sh[1] + sh[2] + sh[3];
    float S2 = sh[4] + sh[5] + sh[6] + sh[7];
    float mu = S * (1.f / Dv);
    float var = S2 * (1.f / Dv) - mu * mu;
    float rs = rsqrtf(var + 1e-5f);
#pragma unroll
    for (int i = 0; i < 4; i++) {
        int j = tid + i * 128;
        size_t idx = (size_t)n * Dv + j;
        float nv = x[idx] + (v[i] - mu) * rs * g[j] + bl[j];
        x[idx] = nv;
        __nv_bfloat16 h, l;
        split_bf16(nv, h, l);
        g_xh[idx] = h;
        g_xl[idx] = l;
    }
}

// -------------------- host driver --------------------
extern "C" void kernel_launch(void* const* d_in, const int* in_sizes, int n_in,
                              void* d_out, int out_size) {
    const int*   tokens = (const int*)d_in[0];
    const float* emb    = (const float*)d_in[1];
    const float* Wq     = (const float*)d_in[2];
    const float* bq     = (const float*)d_in[3];
    const float* Wk     = (const float*)d_in[4];
    const float* bk     = (const float*)d_in[5];
    const float* Wv     = (const float*)d_in[6];
    const float* bvp    = (const float*)d_in[7];
    const float* rfs    = (const float*)d_in[8];
    const float* ln1g   = (const float*)d_in[9];
    const float* ln1b   = (const float*)d_in[10];
    const float* ln2g   = (const float*)d_in[11];
    const float* ln2b   = (const float*)d_in[12];
    const float* WU     = (const float*)d_in[13];
    const float* bU     = (const float*)d_in[14];
    const float* WV     = (const float*)d_in[15];
    const float* bV     = (const float*)d_in[16];
    const float* Wout   = (const float*)d_in[17];
    const float* bout   = (const float*)d_in[18];
    float* out = (float*)d_out;

    static float *px = nullptr, *pa, *pqkv, *pbqkv;
    static __nv_bfloat16 *pxh, *pxl, *phh, *phl, *pwh, *pwl;
    if (!px) {
        cudaGetSymbolAddress((void**)&px, g_x);
        cudaGetSymbolAddress((void**)&pa, g_a);
        cudaGetSymbolAddress((void**)&pqkv, g_qkv);
        cudaGetSymbolAddress((void**)&pbqkv, g_bqkv);
        cudaGetSymbolAddress((void**)&pxh, g_xh);
        cudaGetSymbolAddress((void**)&pxl, g_xl);
        cudaGetSymbolAddress((void**)&phh, g_hh);
        cudaGetSymbolAddress((void**)&phl, g_hl);
        cudaGetSymbolAddress((void**)&pwh, g_wh);
        cudaGetSymbolAddress((void**)&pwl, g_wl);
        cudaFuncSetAttribute(gemm_tc, cudaFuncAttributeMaxDynamicSharedMemorySize, SM_TOTAL);
    }

    // weights -> bf16 hi/lo
    int nq4 = Lv * Dv * Dv / 4;
    convw_qkv<<<(nq4 + 255) / 256, 256>>>(Wq, pwh + OFF_QKV, pwl + OFF_QKV, 0);
    convw_qkv<<<(nq4 + 255) / 256, 256>>>(Wk, pwh + OFF_QKV, pwl + OFF_QKV, 512);
    convw_qkv<<<(nq4 + 255) / 256, 256>>>(Wv, pwh + OFF_QKV, pwl + OFF_QKV, 1024);
    int nu4 = Lv * Dv * FFNv / 4;
    convw4<<<(nu4 + 255) / 256, 256>>>(WU, pwh + OFF_WU, pwl + OFF_WU, nu4);
    convw4<<<(nu4 + 255) / 256, 256>>>(WV, pwh + OFF_WD, pwl + OFF_WD, nu4);
    int no4 = Dv * VOCABv / 4;
    convw4<<<(no4 + 255) / 256, 256>>>(Wout, pwh + OFF_WO, pwl + OFF_WO, no4);
    bias_qkv<<<(Lv * QKVN + 255) / 256, 256>>>(bq, bk, bvp);

    embed_kernel<<<(NTOK * Dv + 255) / 256, 256>>>(tokens, emb);

    for (int l = 0; l < Lv; l++) {
        gemm_tc<<<dim3(QKVN / 128, NTOK / 128), 256, SM_TOTAL>>>(
            pxh, pxl, pwh + OFF_QKV + (size_t)l * Dv * QKVN,
            pwl + OFF_QKV + (size_t)l * Dv * QKVN, pbqkv + l * QKVN,
            pqkv, nullptr, nullptr, NTOK, QKVN, Dv, 0);

        favor_feat<<<dim3(NTOK / 32, Hv), 128>>>(rfs + (size_t)l * Hv * HDv * HDv);
        attn_chunk<<<dim3(NCHUNK, Bv * Hv), 64>>>();
        attn_scan_S<<<Bv * Hv * HDv, 64>>>();
        attn_scan_z<<<Bv * Hv, 64>>>();
        attn_apply<<<dim3(NCHUNK, Bv * Hv), 64>>>();

        ln_add<<<NTOK, 128>>>(pa, ln1g + l * Dv, ln1b + l * Dv, px);

        gemm_tc<<<dim3(FFNv / 128, NTOK / 128), 256, SM_TOTAL>>>(
            pxh, pxl, pwh + OFF_WU + (size_t)l * Dv * FFNv, pwl + OFF_WU + (size_t)l * Dv * FFNv,
            bU + l * FFNv, nullptr, phh, phl, NTOK, FFNv, Dv, 1);
        gemm_tc<<<dim3(Dv / 128, NTOK / 128), 256, SM_TOTAL>>>(
            phh, phl, pwh + OFF_WD + (size_t)l * FFNv * Dv, pwl + OFF_WD + (size_t)l * FFNv * Dv,
            bV + l * Dv, pa, nullptr, nullptr, NTOK, Dv, FFNv, 0);

        ln_add<<<NTOK, 128>>>(pa, ln2g + l * Dv, ln2b + l * Dv, px);
    }

    gemm_tc<<<dim3(VOCABv / 128, NTOK / 128), 256, SM_TOTAL>>>(
        pxh, pxl, pwh + OFF_WO, pwl + OFF_WO, bout, out, nullptr, nullptr,
        NTOK, VOCABv, Dv, 0);
}